// round 9
// baseline (speedup 1.0000x reference)
#include <cuda_runtime.h>
#include <cuda_fp16.h>
#include <cstdint>
#include <cstddef>

#define VOCAB 10000
#define EMBD  100
#define SEQ   80
#define BATCH 1024
#define UNITS 1024

// ---------------- static device scratch (no allocations allowed) ----------------
__device__ float   EP_g[(size_t)VOCAB * UNITS];             // emb@W0x + b0
__device__ __half  H0_g[2][(size_t)BATCH * UNITS];          // h0 fp16 ping-pong
__device__ __half  H1_g[2][(size_t)BATCH * UNITS];          // h1 fp16 ping-pong
__device__ float   P1_g[(size_t)BATCH * UNITS];             // fp32 partial h1_{t-1}@W1h
__device__ __half  W0h_h[(size_t)UNITS * UNITS];            // fp16 k-major
__device__ __half  W1x_h[(size_t)UNITS * UNITS];            // fp16 k-major
__device__ __half  W1h_h[(size_t)UNITS * UNITS];            // fp16 k-major

__device__ __forceinline__ uint32_t smem_u32(const void* p) {
    return (uint32_t)__cvta_generic_to_shared(p);
}

// ---------------- fused prep: zero state + convert weights to fp16 ----------------
__global__ void prep_all(const float* __restrict__ W0h,
                         const float* __restrict__ W1x, const float* __restrict__ W1h) {
    const int nthr = gridDim.x * blockDim.x;
    const int tid  = blockIdx.x * blockDim.x + threadIdx.x;
    {
        const size_t n = (size_t)BATCH * UNITS / 8;     // per buffer, uint4 strides
        uint4 z = make_uint4(0, 0, 0, 0);
        uint4* p0 = (uint4*)&H0_g[1][0];
        uint4* p1 = (uint4*)&H1_g[1][0];
        for (size_t i = tid; i < n; i += nthr) { p0[i] = z; p1[i] = z; }
    }
    for (int i = tid; i < UNITS * UNITS; i += nthr) {
        W0h_h[i] = __float2half_rn(W0h[i]);
        W1x_h[i] = __float2half_rn(W1x[i]);
        W1h_h[i] = __float2half_rn(W1h[i]);
    }
}

// ---------------- EP = emb @ W0x + b0  (fp32, M=10000, K=100, N=1024) ----------------
__global__ void __launch_bounds__(256) ep_kernel(const float* __restrict__ emb,
                                                 const float* __restrict__ W0x,
                                                 const float* __restrict__ b0) {
    __shared__ float se[32][EMBD];
    const int rowbase = blockIdx.y * 32;
    const int colbase = blockIdx.x * 128;
    for (int i = threadIdx.x; i < 32 * EMBD; i += 256) {
        int r = i / EMBD, c = i % EMBD;
        int gr = rowbase + r;
        se[r][c] = (gr < VOCAB) ? emb[(size_t)gr * EMBD + c] : 0.f;
    }
    __syncthreads();
    const int ct = threadIdx.x & 31;
    const int rt = threadIdx.x >> 5;
    const int col = colbase + ct * 4;
    float acc[4][4] = {};
    for (int k = 0; k < EMBD; k++) {
        float4 wv = *(const float4*)&W0x[(size_t)k * UNITS + col];
        #pragma unroll
        for (int i = 0; i < 4; i++) {
            float av = se[rt * 4 + i][k];
            acc[i][0] += av * wv.x; acc[i][1] += av * wv.y;
            acc[i][2] += av * wv.z; acc[i][3] += av * wv.w;
        }
    }
    float4 bv = *(const float4*)&b0[col];
    #pragma unroll
    for (int i = 0; i < 4; i++) {
        int gr = rowbase + rt * 4 + i;
        if (gr < VOCAB) {
            float4 o = make_float4(acc[i][0] + bv.x, acc[i][1] + bv.y,
                                   acc[i][2] + bv.z, acc[i][3] + bv.w);
            *(float4*)&EP_g[(size_t)gr * UNITS + col] = o;
        }
    }
}

// ---------------- shared K=1024 GEMM core: 2-group intra-CTA split-K ----------------
// CTA 256 threads = 2 groups x 4 warps (2x2), tile 64x64, BK=64, per-group 2-stage ring.
// Returns with group 0 holding the fully reduced accumulators.
#define BM 64
#define BN 64
#define BK 64
#define KU 1024
#define KT (KU / BK)

#define APITCH 72                        // 64 + 8 halfs pad (144 B rows)
#define AS_STAGE (BM * APITCH)           // 4608 halfs
#define BS_STAGE (BK * APITCH)           // 4608 halfs
#define STAGE_HALFS (AS_STAGE + BS_STAGE)
#define NSTAGE 4
#define SMEM_BYTES (NSTAGE * STAGE_HALFS * 2)   // 73728 B

__device__ __forceinline__ void gemm_core_k1024(const __half* __restrict__ Ag,
                                                const __half* __restrict__ Bg,
                                                int bm, int bn, float acc[2][4][4]) {
    extern __shared__ __align__(16) __half sm[];
    const int tid  = threadIdx.x;
    const int lane = tid & 31;
    const int wid  = tid >> 5;
    const int grp  = wid >> 2;
    const int gtid = tid & 127;
    const int gw   = wid & 3;
    const int wm   = gw >> 1;
    const int wn   = gw & 1;

    auto gbar = [&]() {
        asm volatile("bar.sync %0, 128;" :: "r"(grp + 1) : "memory");
    };

    auto issue = [&](int kb, int s) {
        __half* As = sm + s * STAGE_HALFS;
        __half* Bs = As + AS_STAGE;
        #pragma unroll
        for (int j = 0; j < 4; j++) {
            int idx = j * 128 + gtid;
            int r = idx >> 3, c = idx & 7;
            const __half* src = Ag + (size_t)(bm + r) * KU + kb * BK + c * 8;
            uint32_t dst = smem_u32(As + r * APITCH + c * 8);
            asm volatile("cp.async.cg.shared.global [%0], [%1], 16;\n" ::"r"(dst), "l"(src));
        }
        #pragma unroll
        for (int j = 0; j < 4; j++) {
            int idx = j * 128 + gtid;
            int r = idx >> 3, c = idx & 7;
            const __half* src = Bg + (size_t)(kb * BK + r) * UNITS + bn + c * 8;
            uint32_t dst = smem_u32(Bs + r * APITCH + c * 8);
            asm volatile("cp.async.cg.shared.global [%0], [%1], 16;\n" ::"r"(dst), "l"(src));
        }
        asm volatile("cp.async.commit_group;\n");
    };

    auto stage_of = [&](int kb) { return grp * 2 + ((kb >> 1) & 1); };

    issue(grp, stage_of(grp));
    issue(grp + 2, stage_of(grp + 2));

    #pragma unroll
    for (int i = 0; i < 2; i++)
        #pragma unroll
        for (int j = 0; j < 4; j++)
            #pragma unroll
            for (int q = 0; q < 4; q++) acc[i][j][q] = 0.f;

    const int arow = (lane & 15);
    const int acol = (lane >> 4) << 3;

    constexpr int ITERS = KT / 2;
    for (int i = 0; i < ITERS; i++) {
        const int kb = grp + 2 * i;
        if (i == ITERS - 1) asm volatile("cp.async.wait_group 0;\n");
        else                asm volatile("cp.async.wait_group 1;\n");
        gbar();
        const int s = stage_of(kb);
        const __half* As = sm + s * STAGE_HALFS;
        const __half* Bs = As + AS_STAGE;

        uint32_t a[2][2][4], bb[2][2][4];
        auto ldfrag = [&](int ks, int buf) {
            #pragma unroll
            for (int mi = 0; mi < 2; mi++) {
                uint32_t addr = smem_u32(As + (wm * 32 + mi * 16 + arow) * APITCH
                                         + ks * 16 + acol);
                asm volatile("ldmatrix.sync.aligned.m8n8.x4.shared.b16 {%0,%1,%2,%3}, [%4];\n"
                             : "=r"(a[buf][mi][0]), "=r"(a[buf][mi][1]),
                               "=r"(a[buf][mi][2]), "=r"(a[buf][mi][3]) : "r"(addr));
            }
            #pragma unroll
            for (int nh = 0; nh < 2; nh++) {
                uint32_t addr = smem_u32(Bs + (ks * 16 + arow) * APITCH
                                         + wn * 32 + nh * 16 + acol);
                asm volatile("ldmatrix.sync.aligned.m8n8.x4.trans.shared.b16 {%0,%1,%2,%3}, [%4];\n"
                             : "=r"(bb[buf][nh][0]), "=r"(bb[buf][nh][1]),
                               "=r"(bb[buf][nh][2]), "=r"(bb[buf][nh][3]) : "r"(addr));
            }
        };

        ldfrag(0, 0);
        #pragma unroll
        for (int ks = 0; ks < 4; ks++) {
            const int cur = ks & 1;
            if (ks < 3) ldfrag(ks + 1, cur ^ 1);
            #pragma unroll
            for (int mi = 0; mi < 2; mi++)
                #pragma unroll
                for (int nn = 0; nn < 4; nn++) {
                    uint32_t b0r = bb[cur][nn >> 1][(nn & 1) * 2];
                    uint32_t b1r = bb[cur][nn >> 1][(nn & 1) * 2 + 1];
                    float* c = acc[mi][nn];
                    asm volatile(
                        "mma.sync.aligned.m16n8k16.row.col.f32.f16.f16.f32 "
                        "{%0,%1,%2,%3}, {%4,%5,%6,%7}, {%8,%9}, {%0,%1,%2,%3};\n"
                        : "+f"(c[0]), "+f"(c[1]), "+f"(c[2]), "+f"(c[3])
                        : "r"(a[cur][mi][0]), "r"(a[cur][mi][1]),
                          "r"(a[cur][mi][2]), "r"(a[cur][mi][3]),
                          "r"(b0r), "r"(b1r));
                }
        }
        gbar();
        if (kb + 4 < KT) issue(kb + 4, stage_of(kb + 4));
    }

    // cross-group reduction: group1 -> smem -> group0
    float* smf = (float*)sm;
    __syncthreads();
    if (grp == 1) {
        #pragma unroll
        for (int mi = 0; mi < 2; mi++)
            #pragma unroll
            for (int nn = 0; nn < 4; nn++)
                #pragma unroll
                for (int q = 0; q < 4; q++)
                    smf[(mi * 16 + nn * 4 + q) * 128 + gtid] = acc[mi][nn][q];
    }
    __syncthreads();
    if (grp == 0) {
        #pragma unroll
        for (int mi = 0; mi < 2; mi++)
            #pragma unroll
            for (int nn = 0; nn < 4; nn++)
                #pragma unroll
                for (int q = 0; q < 4; q++)
                    acc[mi][nn][q] += smf[(mi * 16 + nn * 4 + q) * 128 + gtid];
    }
}

// ---------------- launch1: z=0 -> h0_t ; z=1 -> P1 partial ----------------
__global__ void __launch_bounds__(256) rnn_g1(int t, const int* __restrict__ xids) {
    const int z = blockIdx.z;
    const int pr = (t + 1) & 1;                 // read phase (state t-1)
    const __half* Ag = z ? &H1_g[pr][0] : &H0_g[pr][0];
    const __half* Bg = z ? W1h_h : W0h_h;
    const int bm = blockIdx.y * BM;
    const int bn = blockIdx.x * BN;

    float acc[2][4][4];
    gemm_core_k1024(Ag, Bg, bm, bn, acc);

    const int tid = threadIdx.x, lane = tid & 31, wid = tid >> 5;
    if ((wid >> 2) != 0) return;                // group 0 only
    const int gw = wid & 3, wm = gw >> 1, wn = gw & 1;
    const int r0 = lane >> 2, cp = lane & 3;

    #pragma unroll
    for (int mi = 0; mi < 2; mi++) {
        #pragma unroll
        for (int rr = 0; rr < 2; rr++) {
            const int b = bm + wm * 32 + mi * 16 + r0 + rr * 8;
            if (z == 0) {
                int xi = xids[b * SEQ + t];
                const float* ep = EP_g + (size_t)xi * UNITS;
                #pragma unroll
                for (int nn = 0; nn < 4; nn++) {
                    const int u = bn + wn * 32 + nn * 8 + cp * 2;
                    float v0 = tanhf(acc[mi][nn][rr * 2 + 0] + ep[u]);
                    float v1 = tanhf(acc[mi][nn][rr * 2 + 1] + ep[u + 1]);
                    *(__half2*)&H0_g[t & 1][(size_t)b * UNITS + u] = __floats2half2_rn(v0, v1);
                }
            } else {
                #pragma unroll
                for (int nn = 0; nn < 4; nn++) {
                    const int u = bn + wn * 32 + nn * 8 + cp * 2;
                    *(float2*)&P1_g[(size_t)b * UNITS + u] =
                        make_float2(acc[mi][nn][rr * 2 + 0], acc[mi][nn][rr * 2 + 1]);
                }
            }
        }
    }
}

// ---------------- launch2: h1_t = tanh(h0_t @ W1x + P1 + b1) ----------------
__global__ void __launch_bounds__(256) rnn_g2(int t, const float* __restrict__ b1vec) {
    const __half* Ag = &H0_g[t & 1][0];
    const int bm = blockIdx.y * BM;
    const int bn = blockIdx.x * BN;

    float acc[2][4][4];
    gemm_core_k1024(Ag, W1x_h, bm, bn, acc);

    const int tid = threadIdx.x, lane = tid & 31, wid = tid >> 5;
    if ((wid >> 2) != 0) return;
    const int gw = wid & 3, wm = gw >> 1, wn = gw & 1;
    const int r0 = lane >> 2, cp = lane & 3;

    #pragma unroll
    for (int mi = 0; mi < 2; mi++) {
        #pragma unroll
        for (int rr = 0; rr < 2; rr++) {
            const int b = bm + wm * 32 + mi * 16 + r0 + rr * 8;
            const float* p1 = P1_g + (size_t)b * UNITS;
            #pragma unroll
            for (int nn = 0; nn < 4; nn++) {
                const int u = bn + wn * 32 + nn * 8 + cp * 2;
                float2 pv = *(const float2*)&p1[u];
                float v0 = tanhf(acc[mi][nn][rr * 2 + 0] + pv.x + b1vec[u]);
                float v1 = tanhf(acc[mi][nn][rr * 2 + 1] + pv.y + b1vec[u + 1]);
                *(__half2*)&H1_g[t & 1][(size_t)b * UNITS + u] = __floats2half2_rn(v0, v1);
            }
        }
    }
}

// ---------------- output: sigmoid(h1 @ Wout + bout) ----------------
__global__ void out_kernel(const float* __restrict__ Wout, const float* __restrict__ bout,
                           float* __restrict__ out) {
    const int b = blockIdx.x;
    const __half* h1 = &H1_g[(SEQ - 1) & 1][(size_t)b * UNITS];
    float s = 0.f;
    for (int u = threadIdx.x; u < UNITS; u += blockDim.x)
        s += __half2float(h1[u]) * Wout[u];
    #pragma unroll
    for (int o = 16; o; o >>= 1) s += __shfl_xor_sync(0xffffffff, s, o);
    __shared__ float red[4];
    if ((threadIdx.x & 31) == 0) red[threadIdx.x >> 5] = s;
    __syncthreads();
    if (threadIdx.x == 0) {
        float tot = red[0] + red[1] + red[2] + red[3] + bout[0];
        out[b] = 1.f / (1.f + expf(-tot));
    }
}

// ---------------- launcher ----------------
extern "C" void kernel_launch(void* const* d_in, const int* in_sizes, int n_in,
                              void* d_out, int out_size) {
    (void)in_sizes; (void)n_in; (void)out_size;
    const int*   x    = (const int*)d_in[0];
    const float* emb  = (const float*)d_in[1];
    const float* W0x  = (const float*)d_in[2];
    const float* W0h  = (const float*)d_in[3];
    const float* b0   = (const float*)d_in[4];
    const float* W1x  = (const float*)d_in[5];
    const float* W1h  = (const float*)d_in[6];
    const float* b1   = (const float*)d_in[7];
    const float* Wout = (const float*)d_in[8];
    const float* bout = (const float*)d_in[9];
    float* out = (float*)d_out;

    cudaFuncSetAttribute(rnn_g1, cudaFuncAttributeMaxDynamicSharedMemorySize, SMEM_BYTES);
    cudaFuncSetAttribute(rnn_g2, cudaFuncAttributeMaxDynamicSharedMemorySize, SMEM_BYTES);

    prep_all<<<1184, 256>>>(W0h, W1x, W1h);
    ep_kernel<<<dim3(UNITS / 128, (VOCAB + 31) / 32), 256>>>(emb, W0x, b0);

    dim3 grid1(UNITS / BN, BATCH / BM, 2);   // 16 x 16 x 2 = 512 CTAs
    dim3 grid2(UNITS / BN, BATCH / BM);      // 256 CTAs
    for (int t = 0; t < SEQ; t++) {
        rnn_g1<<<grid1, 256, SMEM_BYTES>>>(t, x);
        rnn_g2<<<grid2, 256, SMEM_BYTES>>>(t, b1);
    }
    out_kernel<<<BATCH, 128>>>(Wout, bout, out);
}

// round 13
// speedup vs baseline: 1.0905x; 1.0905x over previous
#include <cuda_runtime.h>
#include <cuda_fp16.h>
#include <cstdint>
#include <cstddef>

#define VOCAB 10000
#define EMBD  100
#define SEQ   80
#define BATCH 1024
#define UNITS 1024

// ---------------- static device scratch (no allocations allowed) ----------------
__device__ float   EP_g[(size_t)VOCAB * UNITS];             // emb@W0x + b0
__device__ __half  H0_g[2][(size_t)BATCH * UNITS];          // h0 fp16 ping-pong
__device__ __half  H1_g[2][(size_t)BATCH * UNITS];          // h1 fp16 ping-pong
__device__ __half  W0h_h[(size_t)UNITS * UNITS];            // fp16 k-major
__device__ __half  W1x_h[(size_t)UNITS * UNITS];            // fp16 k-major
__device__ __half  W1h_h[(size_t)UNITS * UNITS];            // fp16 k-major

__device__ __forceinline__ uint32_t smem_u32(const void* p) {
    return (uint32_t)__cvta_generic_to_shared(p);
}

// ---------------- fused prep: zero initial state + convert weights to fp16 ----------------
__global__ void prep_all(const float* __restrict__ W0h,
                         const float* __restrict__ W1x, const float* __restrict__ W1h) {
    const int nthr = gridDim.x * blockDim.x;
    const int tid  = blockIdx.x * blockDim.x + threadIdx.x;
    {
        const size_t n = (size_t)BATCH * UNITS / 8;     // per buffer, uint4 strides
        uint4 z = make_uint4(0, 0, 0, 0);
        uint4* p0 = (uint4*)&H0_g[1][0];                // h0_{-1}
        uint4* p1 = (uint4*)&H1_g[0][0];                // h1_{-2}
        for (size_t i = tid; i < n; i += nthr) { p0[i] = z; p1[i] = z; }
    }
    for (int i = tid; i < UNITS * UNITS; i += nthr) {
        W0h_h[i] = __float2half_rn(W0h[i]);
        W1x_h[i] = __float2half_rn(W1x[i]);
        W1h_h[i] = __float2half_rn(W1h[i]);
    }
}

// ---------------- EP = emb @ W0x + b0  (fp32, M=10000, K=100, N=1024) ----------------
__global__ void __launch_bounds__(256) ep_kernel(const float* __restrict__ emb,
                                                 const float* __restrict__ W0x,
                                                 const float* __restrict__ b0) {
    __shared__ float se[32][EMBD];
    const int rowbase = blockIdx.y * 32;
    const int colbase = blockIdx.x * 128;
    for (int i = threadIdx.x; i < 32 * EMBD; i += 256) {
        int r = i / EMBD, c = i % EMBD;
        int gr = rowbase + r;
        se[r][c] = (gr < VOCAB) ? emb[(size_t)gr * EMBD + c] : 0.f;
    }
    __syncthreads();
    const int ct = threadIdx.x & 31;
    const int rt = threadIdx.x >> 5;
    const int col = colbase + ct * 4;
    float acc[4][4] = {};
    for (int k = 0; k < EMBD; k++) {
        float4 wv = *(const float4*)&W0x[(size_t)k * UNITS + col];
        #pragma unroll
        for (int i = 0; i < 4; i++) {
            float av = se[rt * 4 + i][k];
            acc[i][0] += av * wv.x; acc[i][1] += av * wv.y;
            acc[i][2] += av * wv.z; acc[i][3] += av * wv.w;
        }
    }
    float4 bv = *(const float4*)&b0[col];
    #pragma unroll
    for (int i = 0; i < 4; i++) {
        int gr = rowbase + rt * 4 + i;
        if (gr < VOCAB) {
            float4 o = make_float4(acc[i][0] + bv.x, acc[i][1] + bv.y,
                                   acc[i][2] + bv.z, acc[i][3] + bv.w);
            *(float4*)&EP_g[(size_t)gr * UNITS + col] = o;
        }
    }
}

// ---------------- GEMM core: 2-group intra-CTA split-K, dual A/B sources ----------------
// CTA 256 threads = 2 groups x 4 warps (2x2), tile 64x64, BK=64, per-group 2-stage ring.
// kb < khalf reads (A0,B0) at tile kb; kb >= khalf reads (A1,B1) at tile kb-khalf.
// A buffers are [*][1024] row-major; B buffers are [1024][1024] k-major.
// Returns with group 0 holding the fully reduced accumulators.
#define BM 64
#define BN 64
#define BK 64

#define APITCH 72                        // 64 + 8 halfs pad (144 B rows)
#define AS_STAGE (BM * APITCH)           // 4608 halfs
#define BS_STAGE (BK * APITCH)           // 4608 halfs
#define STAGE_HALFS (AS_STAGE + BS_STAGE)
#define NSTAGE 4
#define SMEM_BYTES (NSTAGE * STAGE_HALFS * 2)   // 73728 B

__device__ __forceinline__ void gemm_core(const __half* __restrict__ A0,
                                          const __half* __restrict__ A1,
                                          const __half* __restrict__ B0,
                                          const __half* __restrict__ B1,
                                          int KT_, int khalf,
                                          int bm, int bn, float acc[2][4][4]) {
    extern __shared__ __align__(16) __half sm[];
    const int tid  = threadIdx.x;
    const int lane = tid & 31;
    const int wid  = tid >> 5;
    const int grp  = wid >> 2;
    const int gtid = tid & 127;
    const int gw   = wid & 3;
    const int wm   = gw >> 1;
    const int wn   = gw & 1;

    auto gbar = [&]() {
        asm volatile("bar.sync %0, 128;" :: "r"(grp + 1) : "memory");
    };

    auto issue = [&](int kb, int s) {
        const __half* Asrc; const __half* Bsrc; int kk;
        if (kb < khalf) { Asrc = A0; Bsrc = B0; kk = kb; }
        else            { Asrc = A1; Bsrc = B1; kk = kb - khalf; }
        __half* As = sm + s * STAGE_HALFS;
        __half* Bs = As + AS_STAGE;
        #pragma unroll
        for (int j = 0; j < 4; j++) {
            int idx = j * 128 + gtid;
            int r = idx >> 3, c = idx & 7;
            const __half* src = Asrc + (size_t)(bm + r) * UNITS + kk * BK + c * 8;
            uint32_t dst = smem_u32(As + r * APITCH + c * 8);
            asm volatile("cp.async.cg.shared.global [%0], [%1], 16;\n" ::"r"(dst), "l"(src));
        }
        #pragma unroll
        for (int j = 0; j < 4; j++) {
            int idx = j * 128 + gtid;
            int r = idx >> 3, c = idx & 7;
            const __half* src = Bsrc + (size_t)(kk * BK + r) * UNITS + bn + c * 8;
            uint32_t dst = smem_u32(Bs + r * APITCH + c * 8);
            asm volatile("cp.async.cg.shared.global [%0], [%1], 16;\n" ::"r"(dst), "l"(src));
        }
        asm volatile("cp.async.commit_group;\n");
    };

    auto stage_of = [&](int kb) { return grp * 2 + ((kb >> 1) & 1); };

    issue(grp, stage_of(grp));
    issue(grp + 2, stage_of(grp + 2));

    #pragma unroll
    for (int i = 0; i < 2; i++)
        #pragma unroll
        for (int j = 0; j < 4; j++)
            #pragma unroll
            for (int q = 0; q < 4; q++) acc[i][j][q] = 0.f;

    const int arow = (lane & 15);
    const int acol = (lane >> 4) << 3;

    const int ITERS = KT_ / 2;
    for (int i = 0; i < ITERS; i++) {
        const int kb = grp + 2 * i;
        if (i == ITERS - 1) asm volatile("cp.async.wait_group 0;\n");
        else                asm volatile("cp.async.wait_group 1;\n");
        gbar();
        const int s = stage_of(kb);
        const __half* As = sm + s * STAGE_HALFS;
        const __half* Bs = As + AS_STAGE;

        uint32_t a[2][2][4], bb[2][2][4];
        auto ldfrag = [&](int ks, int buf) {
            #pragma unroll
            for (int mi = 0; mi < 2; mi++) {
                uint32_t addr = smem_u32(As + (wm * 32 + mi * 16 + arow) * APITCH
                                         + ks * 16 + acol);
                asm volatile("ldmatrix.sync.aligned.m8n8.x4.shared.b16 {%0,%1,%2,%3}, [%4];\n"
                             : "=r"(a[buf][mi][0]), "=r"(a[buf][mi][1]),
                               "=r"(a[buf][mi][2]), "=r"(a[buf][mi][3]) : "r"(addr));
            }
            #pragma unroll
            for (int nh = 0; nh < 2; nh++) {
                uint32_t addr = smem_u32(Bs + (ks * 16 + arow) * APITCH
                                         + wn * 32 + nh * 16 + acol);
                asm volatile("ldmatrix.sync.aligned.m8n8.x4.trans.shared.b16 {%0,%1,%2,%3}, [%4];\n"
                             : "=r"(bb[buf][nh][0]), "=r"(bb[buf][nh][1]),
                               "=r"(bb[buf][nh][2]), "=r"(bb[buf][nh][3]) : "r"(addr));
            }
        };

        ldfrag(0, 0);
        #pragma unroll
        for (int ks = 0; ks < 4; ks++) {
            const int cur = ks & 1;
            if (ks < 3) ldfrag(ks + 1, cur ^ 1);
            #pragma unroll
            for (int mi = 0; mi < 2; mi++)
                #pragma unroll
                for (int nn = 0; nn < 4; nn++) {
                    uint32_t b0r = bb[cur][nn >> 1][(nn & 1) * 2];
                    uint32_t b1r = bb[cur][nn >> 1][(nn & 1) * 2 + 1];
                    float* c = acc[mi][nn];
                    asm volatile(
                        "mma.sync.aligned.m16n8k16.row.col.f32.f16.f16.f32 "
                        "{%0,%1,%2,%3}, {%4,%5,%6,%7}, {%8,%9}, {%0,%1,%2,%3};\n"
                        : "+f"(c[0]), "+f"(c[1]), "+f"(c[2]), "+f"(c[3])
                        : "r"(a[cur][mi][0]), "r"(a[cur][mi][1]),
                          "r"(a[cur][mi][2]), "r"(a[cur][mi][3]),
                          "r"(b0r), "r"(b1r));
                }
        }
        gbar();
        if (kb + 4 < KT_) issue(kb + 4, stage_of(kb + 4));
    }

    // cross-group reduction: group1 -> smem -> group0
    float* smf = (float*)sm;
    __syncthreads();
    if (grp == 1) {
        #pragma unroll
        for (int mi = 0; mi < 2; mi++)
            #pragma unroll
            for (int nn = 0; nn < 4; nn++)
                #pragma unroll
                for (int q = 0; q < 4; q++)
                    smf[(mi * 16 + nn * 4 + q) * 128 + gtid] = acc[mi][nn][q];
    }
    __syncthreads();
    if (grp == 0) {
        #pragma unroll
        for (int mi = 0; mi < 2; mi++)
            #pragma unroll
            for (int nn = 0; nn < 4; nn++)
                #pragma unroll
                for (int q = 0; q < 4; q++)
                    acc[mi][nn][q] += smf[(mi * 16 + nn * 4 + q) * 128 + gtid];
    }
}

// ---------------- one launch per step ----------------
// z=0 (heavy, scheduled first): h1_{t-1} = tanh(h0_{t-1}@W1x + h1_{t-2}@W1h + b1), K=2048
//                               (at t==0 writes the true initial state h1_{-1} = 0)
// z=1:                          h0_t = tanh(EP[x[b,t]] + h0_{t-1}@W0h),              K=1024
// Reads: h0_{t-1} = H0_g[(t+1)&1], h1_{t-2} = H1_g[t&1]
// Writes: h1_{t-1} -> H1_g[(t+1)&1], h0_t -> H0_g[t&1]
__global__ void __launch_bounds__(256) rnn_step(int t, const int* __restrict__ xids,
                                                const float* __restrict__ b1vec) {
    const int z  = blockIdx.z;
    const int bm = blockIdx.y * BM;
    const int bn = blockIdx.x * BN;
    const __half* h0prev = &H0_g[(t + 1) & 1][0];

    float acc[2][4][4];
    if (z == 0) {
        gemm_core(h0prev, &H1_g[t & 1][0], W1x_h, W1h_h, 32, 16, bm, bn, acc);
    } else {
        // K=1024, single source: khalf = KT so the (A1,B1) branch is never taken
        gemm_core(h0prev, h0prev, W0h_h, W0h_h, 16, 16, bm, bn, acc);
    }

    const int tid = threadIdx.x, lane = tid & 31, wid = tid >> 5;
    if ((wid >> 2) != 0) return;                // group 0 only
    const int gw = wid & 3, wm = gw >> 1, wn = gw & 1;
    const int r0 = lane >> 2, cp = lane & 3;

    #pragma unroll
    for (int mi = 0; mi < 2; mi++) {
        #pragma unroll
        for (int rr = 0; rr < 2; rr++) {
            const int b = bm + wm * 32 + mi * 16 + r0 + rr * 8;
            if (z == 0) {
                __half* dst = &H1_g[(t + 1) & 1][(size_t)b * UNITS];
                #pragma unroll
                for (int nn = 0; nn < 4; nn++) {
                    const int u = bn + wn * 32 + nn * 8 + cp * 2;
                    float v0 = tanhf(acc[mi][nn][rr * 2 + 0] + b1vec[u]);
                    float v1 = tanhf(acc[mi][nn][rr * 2 + 1] + b1vec[u + 1]);
                    if (t == 0) { v0 = 0.f; v1 = 0.f; }     // true initial h1_{-1}
                    *(__half2*)&dst[u] = __floats2half2_rn(v0, v1);
                }
            } else {
                int xi = xids[b * SEQ + t];
                const float* ep = EP_g + (size_t)xi * UNITS;
                __half* dst = &H0_g[t & 1][(size_t)b * UNITS];
                #pragma unroll
                for (int nn = 0; nn < 4; nn++) {
                    const int u = bn + wn * 32 + nn * 8 + cp * 2;
                    float v0 = tanhf(acc[mi][nn][rr * 2 + 0] + ep[u]);
                    float v1 = tanhf(acc[mi][nn][rr * 2 + 1] + ep[u + 1]);
                    *(__half2*)&dst[u] = __floats2half2_rn(v0, v1);
                }
            }
        }
    }
}

// ---------------- output: sigmoid(h1 @ Wout + bout) ----------------
__global__ void out_kernel(const float* __restrict__ Wout, const float* __restrict__ bout,
                           float* __restrict__ out) {
    const int b = blockIdx.x;
    const __half* h1 = &H1_g[1][(size_t)b * UNITS];     // h1_{SEQ-1}: tail t=SEQ, (SEQ+1)&1 = 1
    float s = 0.f;
    for (int u = threadIdx.x; u < UNITS; u += blockDim.x)
        s += __half2float(h1[u]) * Wout[u];
    #pragma unroll
    for (int o = 16; o; o >>= 1) s += __shfl_xor_sync(0xffffffff, s, o);
    __shared__ float red[4];
    if ((threadIdx.x & 31) == 0) red[threadIdx.x >> 5] = s;
    __syncthreads();
    if (threadIdx.x == 0) {
        float tot = red[0] + red[1] + red[2] + red[3] + bout[0];
        out[b] = 1.f / (1.f + expf(-tot));
    }
}

// ---------------- launcher ----------------
extern "C" void kernel_launch(void* const* d_in, const int* in_sizes, int n_in,
                              void* d_out, int out_size) {
    (void)in_sizes; (void)n_in; (void)out_size;
    const int*   x    = (const int*)d_in[0];
    const float* emb  = (const float*)d_in[1];
    const float* W0x  = (const float*)d_in[2];
    const float* W0h  = (const float*)d_in[3];
    const float* b0   = (const float*)d_in[4];
    const float* W1x  = (const float*)d_in[5];
    const float* W1h  = (const float*)d_in[6];
    const float* b1   = (const float*)d_in[7];
    const float* Wout = (const float*)d_in[8];
    const float* bout = (const float*)d_in[9];
    float* out = (float*)d_out;

    cudaFuncSetAttribute(rnn_step, cudaFuncAttributeMaxDynamicSharedMemorySize, SMEM_BYTES);

    prep_all<<<1184, 256>>>(W0h, W1x, W1h);
    ep_kernel<<<dim3(UNITS / 128, (VOCAB + 31) / 32), 256>>>(emb, W0x, b0);

    dim3 gridS(UNITS / BN, BATCH / BM, 2);   // both layers in one launch
    dim3 gridT(UNITS / BN, BATCH / BM, 1);   // tail: h1_{SEQ-1} only (z=0 path)
    for (int t = 0; t < SEQ; t++)
        rnn_step<<<gridS, 256, SMEM_BYTES>>>(t, x, b1);
    rnn_step<<<gridT, 256, SMEM_BYTES>>>(SEQ, x, b1);

    out_kernel<<<BATCH, 128>>>(Wout, bout, out);
}

// round 14
// speedup vs baseline: 1.1523x; 1.0568x over previous
#include <cuda_runtime.h>
#include <cuda_fp16.h>
#include <cstdint>
#include <cstddef>

#define VOCAB 10000
#define EMBD  100
#define SEQ   80
#define BATCH 1024
#define UNITS 1024

// ---------------- static device scratch (no allocations allowed) ----------------
__device__ float   EP_g[(size_t)VOCAB * UNITS];             // emb@W0x + b0
__device__ __half  H0_g[2][(size_t)BATCH * UNITS];          // h0 fp16 ping-pong
__device__ __half  H1_g[2][(size_t)BATCH * UNITS];          // h1 fp16 ping-pong
__device__ __half  W0h_h[(size_t)UNITS * UNITS];            // fp16 k-major
__device__ __half  W1x_h[(size_t)UNITS * UNITS];            // fp16 k-major
__device__ __half  W1h_h[(size_t)UNITS * UNITS];            // fp16 k-major

__device__ __forceinline__ uint32_t smem_u32(const void* p) {
    return (uint32_t)__cvta_generic_to_shared(p);
}

// ---------------- fused prep: zero initial state + convert weights to fp16 ----------------
__global__ void prep_all(const float* __restrict__ W0h,
                         const float* __restrict__ W1x, const float* __restrict__ W1h) {
    const int nthr = gridDim.x * blockDim.x;
    const int tid  = blockIdx.x * blockDim.x + threadIdx.x;
    {
        const size_t n = (size_t)BATCH * UNITS / 8;     // per buffer, uint4 strides
        uint4 z = make_uint4(0, 0, 0, 0);
        uint4* p0 = (uint4*)&H0_g[1][0];                // h0_{-1}
        uint4* p1 = (uint4*)&H1_g[0][0];                // h1_{-2}
        for (size_t i = tid; i < n; i += nthr) { p0[i] = z; p1[i] = z; }
    }
    for (int i = tid; i < UNITS * UNITS; i += nthr) {
        W0h_h[i] = __float2half_rn(W0h[i]);
        W1x_h[i] = __float2half_rn(W1x[i]);
        W1h_h[i] = __float2half_rn(W1h[i]);
    }
}

// ---------------- EP = emb @ W0x + b0  (fp32, M=10000, K=100, N=1024) ----------------
__global__ void __launch_bounds__(256) ep_kernel(const float* __restrict__ emb,
                                                 const float* __restrict__ W0x,
                                                 const float* __restrict__ b0) {
    __shared__ float se[32][EMBD];
    const int rowbase = blockIdx.y * 32;
    const int colbase = blockIdx.x * 128;
    for (int i = threadIdx.x; i < 32 * EMBD; i += 256) {
        int r = i / EMBD, c = i % EMBD;
        int gr = rowbase + r;
        se[r][c] = (gr < VOCAB) ? emb[(size_t)gr * EMBD + c] : 0.f;
    }
    __syncthreads();
    const int ct = threadIdx.x & 31;
    const int rt = threadIdx.x >> 5;
    const int col = colbase + ct * 4;
    float acc[4][4] = {};
    for (int k = 0; k < EMBD; k++) {
        float4 wv = *(const float4*)&W0x[(size_t)k * UNITS + col];
        #pragma unroll
        for (int i = 0; i < 4; i++) {
            float av = se[rt * 4 + i][k];
            acc[i][0] += av * wv.x; acc[i][1] += av * wv.y;
            acc[i][2] += av * wv.z; acc[i][3] += av * wv.w;
        }
    }
    float4 bv = *(const float4*)&b0[col];
    #pragma unroll
    for (int i = 0; i < 4; i++) {
        int gr = rowbase + rt * 4 + i;
        if (gr < VOCAB) {
            float4 o = make_float4(acc[i][0] + bv.x, acc[i][1] + bv.y,
                                   acc[i][2] + bv.z, acc[i][3] + bv.w);
            *(float4*)&EP_g[(size_t)gr * UNITS + col] = o;
        }
    }
}

// ---------------- GEMM core: 2-group intra-CTA split-K, CTA tile 64x128 ----------------
// CTA 256 threads = 2 groups x 4 warps (2m x 2n), warp tile 32x64, BK=64.
// kb < khalf reads (A0,B0) at tile kb; kb >= khalf reads (A1,B1) at tile kb-khalf.
// A buffers are [*][1024] row-major; B buffers are [1024][1024] k-major.
// Returns with group 0 holding the fully reduced accumulators.
#define BM 64
#define BN 128
#define BK 64

#define APITCH 72                        // 64 + 8 halfs pad (144 B rows)
#define BPITCH 136                       // 128 + 8 halfs pad (272 B rows)
#define AS_STAGE (BM * APITCH)           // 4608 halfs
#define BS_STAGE (BK * BPITCH)           // 8704 halfs
#define STAGE_HALFS (AS_STAGE + BS_STAGE)
#define NSTAGE 4
#define SMEM_BYTES (NSTAGE * STAGE_HALFS * 2)   // 106496 B -> 2 CTAs/SM

__device__ __forceinline__ void gemm_core(const __half* __restrict__ A0,
                                          const __half* __restrict__ A1,
                                          const __half* __restrict__ B0,
                                          const __half* __restrict__ B1,
                                          int KT_, int khalf,
                                          int bm, int bn, float acc[2][8][4]) {
    extern __shared__ __align__(16) __half sm[];
    const int tid  = threadIdx.x;
    const int lane = tid & 31;
    const int wid  = tid >> 5;
    const int grp  = wid >> 2;
    const int gtid = tid & 127;
    const int gw   = wid & 3;
    const int wm   = gw >> 1;           // 2 warp rows (32 each)
    const int wn   = gw & 1;            // 2 warp cols (64 each)

    auto gbar = [&]() {
        asm volatile("bar.sync %0, 128;" :: "r"(grp + 1) : "memory");
    };

    auto issue = [&](int kb, int s) {
        const __half* Asrc; const __half* Bsrc; int kk;
        if (kb < khalf) { Asrc = A0; Bsrc = B0; kk = kb; }
        else            { Asrc = A1; Bsrc = B1; kk = kb - khalf; }
        __half* As = sm + s * STAGE_HALFS;
        __half* Bs = As + AS_STAGE;
        // A tile 64x64 halfs = 512 16B chunks, 4 per thread
        #pragma unroll
        for (int j = 0; j < 4; j++) {
            int idx = j * 128 + gtid;
            int r = idx >> 3, c = idx & 7;
            const __half* src = Asrc + (size_t)(bm + r) * UNITS + kk * BK + c * 8;
            uint32_t dst = smem_u32(As + r * APITCH + c * 8);
            asm volatile("cp.async.cg.shared.global [%0], [%1], 16;\n" ::"r"(dst), "l"(src));
        }
        // B tile 64x128 halfs = 1024 16B chunks, 8 per thread
        #pragma unroll
        for (int j = 0; j < 8; j++) {
            int idx = j * 128 + gtid;
            int r = idx >> 4, c = idx & 15;
            const __half* src = Bsrc + (size_t)(kk * BK + r) * UNITS + bn + c * 8;
            uint32_t dst = smem_u32(Bs + r * BPITCH + c * 8);
            asm volatile("cp.async.cg.shared.global [%0], [%1], 16;\n" ::"r"(dst), "l"(src));
        }
        asm volatile("cp.async.commit_group;\n");
    };

    auto stage_of = [&](int kb) { return grp * 2 + ((kb >> 1) & 1); };

    issue(grp, stage_of(grp));
    issue(grp + 2, stage_of(grp + 2));

    #pragma unroll
    for (int i = 0; i < 2; i++)
        #pragma unroll
        for (int j = 0; j < 8; j++)
            #pragma unroll
            for (int q = 0; q < 4; q++) acc[i][j][q] = 0.f;

    const int arow = (lane & 15);
    const int acol = (lane >> 4) << 3;

    const int ITERS = KT_ / 2;
    for (int i = 0; i < ITERS; i++) {
        const int kb = grp + 2 * i;
        if (i == ITERS - 1) asm volatile("cp.async.wait_group 0;\n");
        else                asm volatile("cp.async.wait_group 1;\n");
        gbar();
        const int s = stage_of(kb);
        const __half* As = sm + s * STAGE_HALFS;
        const __half* Bs = As + AS_STAGE;

        #pragma unroll
        for (int ks = 0; ks < 4; ks++) {
            uint32_t a[2][4], bb[4][4];
            #pragma unroll
            for (int mi = 0; mi < 2; mi++) {
                uint32_t addr = smem_u32(As + (wm * 32 + mi * 16 + arow) * APITCH
                                         + ks * 16 + acol);
                asm volatile("ldmatrix.sync.aligned.m8n8.x4.shared.b16 {%0,%1,%2,%3}, [%4];\n"
                             : "=r"(a[mi][0]), "=r"(a[mi][1]),
                               "=r"(a[mi][2]), "=r"(a[mi][3]) : "r"(addr));
            }
            #pragma unroll
            for (int nh = 0; nh < 4; nh++) {
                uint32_t addr = smem_u32(Bs + (ks * 16 + arow) * BPITCH
                                         + wn * 64 + nh * 16 + acol);
                asm volatile("ldmatrix.sync.aligned.m8n8.x4.trans.shared.b16 {%0,%1,%2,%3}, [%4];\n"
                             : "=r"(bb[nh][0]), "=r"(bb[nh][1]),
                               "=r"(bb[nh][2]), "=r"(bb[nh][3]) : "r"(addr));
            }
            #pragma unroll
            for (int mi = 0; mi < 2; mi++)
                #pragma unroll
                for (int nn = 0; nn < 8; nn++) {
                    uint32_t b0r = bb[nn >> 1][(nn & 1) * 2];
                    uint32_t b1r = bb[nn >> 1][(nn & 1) * 2 + 1];
                    float* c = acc[mi][nn];
                    asm volatile(
                        "mma.sync.aligned.m16n8k16.row.col.f32.f16.f16.f32 "
                        "{%0,%1,%2,%3}, {%4,%5,%6,%7}, {%8,%9}, {%0,%1,%2,%3};\n"
                        : "+f"(c[0]), "+f"(c[1]), "+f"(c[2]), "+f"(c[3])
                        : "r"(a[mi][0]), "r"(a[mi][1]),
                          "r"(a[mi][2]), "r"(a[mi][3]),
                          "r"(b0r), "r"(b1r));
                }
        }
        gbar();
        if (kb + 4 < KT_) issue(kb + 4, stage_of(kb + 4));
    }

    // cross-group reduction: group1 -> smem -> group0 (64 floats/thread = 32 KB)
    float* smf = (float*)sm;
    __syncthreads();
    if (grp == 1) {
        #pragma unroll
        for (int mi = 0; mi < 2; mi++)
            #pragma unroll
            for (int nn = 0; nn < 8; nn++)
                #pragma unroll
                for (int q = 0; q < 4; q++)
                    smf[(mi * 32 + nn * 4 + q) * 128 + gtid] = acc[mi][nn][q];
    }
    __syncthreads();
    if (grp == 0) {
        #pragma unroll
        for (int mi = 0; mi < 2; mi++)
            #pragma unroll
            for (int nn = 0; nn < 8; nn++)
                #pragma unroll
                for (int q = 0; q < 4; q++)
                    acc[mi][nn][q] += smf[(mi * 32 + nn * 4 + q) * 128 + gtid];
    }
}

// ---------------- one launch per step ----------------
// z=0 (heavy): h1_{t-1} = tanh(h0_{t-1}@W1x + h1_{t-2}@W1h + b1), K=2048
//              (at t==0 writes the true initial state h1_{-1} = 0)
// z=1:         h0_t = tanh(EP[x[b,t]] + h0_{t-1}@W0h),              K=1024
// Reads: h0_{t-1} = H0_g[(t+1)&1], h1_{t-2} = H1_g[t&1]
// Writes: h1_{t-1} -> H1_g[(t+1)&1], h0_t -> H0_g[t&1]
__global__ void __launch_bounds__(256, 2) rnn_step(int t, const int* __restrict__ xids,
                                                   const float* __restrict__ b1vec) {
    const int z  = blockIdx.z;
    const int bm = blockIdx.y * BM;
    const int bn = blockIdx.x * BN;
    const __half* h0prev = &H0_g[(t + 1) & 1][0];

    float acc[2][8][4];
    if (z == 0) {
        gemm_core(h0prev, &H1_g[t & 1][0], W1x_h, W1h_h, 32, 16, bm, bn, acc);
    } else {
        // K=1024, single source: khalf = KT so the (A1,B1) branch is never taken
        gemm_core(h0prev, h0prev, W0h_h, W0h_h, 16, 16, bm, bn, acc);
    }

    const int tid = threadIdx.x, lane = tid & 31, wid = tid >> 5;
    if ((wid >> 2) != 0) return;                // group 0 only
    const int gw = wid & 3, wm = gw >> 1, wn = gw & 1;
    const int r0 = lane >> 2, cp = lane & 3;

    #pragma unroll
    for (int mi = 0; mi < 2; mi++) {
        #pragma unroll
        for (int rr = 0; rr < 2; rr++) {
            const int b = bm + wm * 32 + mi * 16 + r0 + rr * 8;
            if (z == 0) {
                __half* dst = &H1_g[(t + 1) & 1][(size_t)b * UNITS];
                #pragma unroll
                for (int nn = 0; nn < 8; nn++) {
                    const int u = bn + wn * 64 + nn * 8 + cp * 2;
                    float v0 = tanhf(acc[mi][nn][rr * 2 + 0] + b1vec[u]);
                    float v1 = tanhf(acc[mi][nn][rr * 2 + 1] + b1vec[u + 1]);
                    if (t == 0) { v0 = 0.f; v1 = 0.f; }     // true initial h1_{-1}
                    *(__half2*)&dst[u] = __floats2half2_rn(v0, v1);
                }
            } else {
                int xi = xids[b * SEQ + t];
                const float* ep = EP_g + (size_t)xi * UNITS;
                __half* dst = &H0_g[t & 1][(size_t)b * UNITS];
                #pragma unroll
                for (int nn = 0; nn < 8; nn++) {
                    const int u = bn + wn * 64 + nn * 8 + cp * 2;
                    float v0 = tanhf(acc[mi][nn][rr * 2 + 0] + ep[u]);
                    float v1 = tanhf(acc[mi][nn][rr * 2 + 1] + ep[u + 1]);
                    *(__half2*)&dst[u] = __floats2half2_rn(v0, v1);
                }
            }
        }
    }
}

// ---------------- output: sigmoid(h1 @ Wout + bout) ----------------
__global__ void out_kernel(const float* __restrict__ Wout, const float* __restrict__ bout,
                           float* __restrict__ out) {
    const int b = blockIdx.x;
    const __half* h1 = &H1_g[1][(size_t)b * UNITS];     // h1_{SEQ-1}: tail t=SEQ, (SEQ+1)&1 = 1
    float s = 0.f;
    for (int u = threadIdx.x; u < UNITS; u += blockDim.x)
        s += __half2float(h1[u]) * Wout[u];
    #pragma unroll
    for (int o = 16; o; o >>= 1) s += __shfl_xor_sync(0xffffffff, s, o);
    __shared__ float red[4];
    if ((threadIdx.x & 31) == 0) red[threadIdx.x >> 5] = s;
    __syncthreads();
    if (threadIdx.x == 0) {
        float tot = red[0] + red[1] + red[2] + red[3] + bout[0];
        out[b] = 1.f / (1.f + expf(-tot));
    }
}

// ---------------- launcher ----------------
extern "C" void kernel_launch(void* const* d_in, const int* in_sizes, int n_in,
                              void* d_out, int out_size) {
    (void)in_sizes; (void)n_in; (void)out_size;
    const int*   x    = (const int*)d_in[0];
    const float* emb  = (const float*)d_in[1];
    const float* W0x  = (const float*)d_in[2];
    const float* W0h  = (const float*)d_in[3];
    const float* b0   = (const float*)d_in[4];
    const float* W1x  = (const float*)d_in[5];
    const float* W1h  = (const float*)d_in[6];
    const float* b1   = (const float*)d_in[7];
    const float* Wout = (const float*)d_in[8];
    const float* bout = (const float*)d_in[9];
    float* out = (float*)d_out;

    cudaFuncSetAttribute(rnn_step, cudaFuncAttributeMaxDynamicSharedMemorySize, SMEM_BYTES);

    prep_all<<<1184, 256>>>(W0h, W1x, W1h);
    ep_kernel<<<dim3(UNITS / 128, (VOCAB + 31) / 32), 256>>>(emb, W0x, b0);

    dim3 gridS(UNITS / BN, BATCH / BM, 2);   // 8 x 16 x 2 = 256 CTAs, single wave
    dim3 gridT(UNITS / BN, BATCH / BM, 1);   // tail: h1_{SEQ-1} only (z=0 path)
    for (int t = 0; t < SEQ; t++)
        rnn_step<<<gridS, 256, SMEM_BYTES>>>(t, x, b1);
    rnn_step<<<gridT, 256, SMEM_BYTES>>>(SEQ, x, b1);

    out_kernel<<<BATCH, 128>>>(Wout, bout, out);
}